// round 12
// baseline (speedup 1.0000x reference)
#include <cuda_runtime.h>
#include <math.h>

#define DIM    1024
#define HALF   512
#define NMAX   65536
#define P2B    512          // pass2 blocks
#define P2ROWS 128          // rows per pass2 block
#define NBPRE  64           // pre-blocks inside pass1
#define NBPOST 128          // post blocks

// ---------------- scratch (device globals) ----------------------------------------
__device__ float    g_qpart[NBPRE * HALF];   // Wq GEMV partials
__device__ float    g_qk[DIM];               // Wk @ q
__device__ float    g_s[NMAX];               // raw scores
__device__ float    g_invn[NMAX];            // 1/||k_init[n]||
__device__ float    g_sfA[512];              // score-sum slots
__device__ float    g_sfB[512];              // score-sumsq slots
__device__ float    g_epart[P2B];            // per-pass2-block exp sums
__device__ float    g_zpart[P2B * DIM];      // pass2 partial row-sums
__device__ float    g_vpart[NBPOST * DIM];   // z@Wv partials
__device__ float    g_mpart[NBPOST * DIM];   // ctx@Wm partials
__device__ unsigned g_syncA = 0;             // barrier counter (pre blocks)
__device__ unsigned g_syncB = 0;             // barrier counter (post)
__device__ unsigned g_qkdone = 0;            // qk-ready flag (reset by pass2)

// ---------------- generation-based grid barrier (participants resident) ------------
__device__ __forceinline__ void grid_sync(unsigned* ctr, unsigned nb) {
    __syncthreads();
    if (threadIdx.x == 0) {
        __threadfence();
        unsigned old = atomicAdd(ctr, 1u);
        unsigned target = (old / nb + 1u) * nb;
        while (*(volatile unsigned*)ctr < target) __nanosleep(64);
        __threadfence();
    }
    __syncthreads();
}

__device__ __forceinline__ void l2_prefetch(const void* p) {
    asm volatile("prefetch.global.L2 [%0];" :: "l"(p));
}

// ---------------- kernel 1: fused pre + LEAN pass 1 (N/8 blocks x 256 thr) ---------
// Blocks 0..63 compute qk = Wk @ (l2norm(q_init)@Wq + bq), then raise the flag.
// While pre runs, all other resident blocks PREFETCH their own K rows into L2,
// so the post-flag streaming starts from L2 instead of cold DRAM.
__global__ void __launch_bounds__(256)
kern_pass1(const float* __restrict__ Kmat,
           const float* __restrict__ q_init,
           const float* __restrict__ Wq,
           const float* __restrict__ Wk,
           const float* __restrict__ bq) {
    __shared__ float sh[DIM + HALF];   // pre: qn|q ; pass1: qk in [0..DIM)
    __shared__ float red[8];
    __shared__ unsigned ready_sh;
    int b = blockIdx.x, t = threadIdx.x, w = t >> 5, l = t & 31;

    // ===================== pre (blocks 0..63 only) =====================
    if (b < NBPRE) {
        if (t < 8) {                  // reset stat slots each replay
            g_sfA[b * 8 + t] = 0.f;
            g_sfB[b * 8 + t] = 0.f;
        }

        // q l2norm (redundant per pre-block; 4 KB, L2 hit)
        float4 v = ((const float4*)q_init)[t];
        float ss = v.x * v.x + v.y * v.y + v.z * v.z + v.w * v.w;
        #pragma unroll
        for (int o = 16; o; o >>= 1) ss += __shfl_xor_sync(0xFFFFFFFFu, ss, o);
        if (l == 0) red[w] = ss;
        __syncthreads();
        if (t == 0) {
            float tot = 0.f;
            #pragma unroll
            for (int i = 0; i < 8; i++) tot += red[i];
            red[0] = 1.0f / fmaxf(sqrtf(tot), 1e-12f);
        }
        __syncthreads();
        float inv = red[0];
        ((float4*)sh)[t] = make_float4(v.x * inv, v.y * inv, v.z * inv, v.w * inv);
        __syncthreads();

        // Wq GEMV partial: pre-block b owns d-rows [b*16, b*16+16); float2 cols
        {
            const float2* W2 = (const float2*)(Wq + (size_t)b * 16 * HALF);
            float2 a = make_float2(0.f, 0.f);
            #pragma unroll
            for (int d = 0; d < 16; d++) {
                float x = sh[b * 16 + d];
                float2 wv = W2[d * (HALF / 2) + t];
                a.x += x * wv.x;
                a.y += x * wv.y;
            }
            ((float2*)(g_qpart + b * HALF))[t] = a;
        }

        grid_sync(&g_syncA, NBPRE);   // among the 64 pre blocks (wave-1 resident)

        // combine q = bq + sum(partials) into sh[DIM..DIM+HALF)
        #pragma unroll
        for (int j = 0; j < 2; j++) {
            int c = t + j * 256;
            float acc = bq[c];
            #pragma unroll 16
            for (int p = 0; p < NBPRE; p++) acc += g_qpart[p * HALF + c];
            sh[DIM + c] = acc;
        }
        __syncthreads();

        // Wk GEMV: pre-block b owns qk rows [b*16, b*16+16); 8 warps x 2 rows
        #pragma unroll
        for (int r = 0; r < 2; r++) {
            int d = b * 16 + w * 2 + r;
            const float4* row = (const float4*)(Wk + (size_t)d * HALF);
            const float4* q4  = (const float4*)(sh + DIM);
            float acc = 0.f;
            #pragma unroll
            for (int i = 0; i < 4; i++) {
                float4 vv = row[i * 32 + l];
                float4 qq = q4[i * 32 + l];
                acc += vv.x * qq.x + vv.y * qq.y + vv.z * qq.z + vv.w * qq.w;
            }
            #pragma unroll
            for (int o = 16; o; o >>= 1) acc += __shfl_xor_sync(0xFFFFFFFFu, acc, o);
            if (l == 0) g_qk[d] = acc;
        }
        __syncthreads();
        if (t == 0) {
            __threadfence();
            atomicAdd(&g_qkdone, 1u);
        }
        __syncthreads();
    }

    // ===================== lean pass 1 (all blocks) =====================
    // If pre is still running, prefetch this block's 8 K rows (32 KB) into L2
    // — fire-and-forget, keeps DRAM busy during the serial pre head.
    if (t == 0) ready_sh = *(volatile unsigned*)&g_qkdone;
    __syncthreads();
    if (ready_sh < (unsigned)NBPRE) {
        const char* base = (const char*)(Kmat + (size_t)b * 8 * DIM) + (size_t)t * 128;
        l2_prefetch(base);   // 256 threads x 128 B = 32 KB = the block's rows
    }

    // poll the flag (pre blocks pass instantly; later waves see it set)
    if (t == 0) {
        while (*(volatile unsigned*)&g_qkdone < (unsigned)NBPRE) __nanosleep(64);
    }
    __syncthreads();

    // qk into shared
    #pragma unroll
    for (int i = 0; i < 4; i++) sh[t + i * 256] = g_qk[t + i * 256];
    __syncthreads();

    long n = (long)b * 8 + w;
    const float4* row = (const float4*)(Kmat + n * DIM);
    const float4* q4  = (const float4*)sh;
    float ss = 0.f, dp = 0.f;
    #pragma unroll
    for (int i = 0; i < 8; i++) {
        float4 v = row[i * 32 + l];
        float4 q = q4[i * 32 + l];
        ss += v.x * v.x + v.y * v.y + v.z * v.z + v.w * v.w;
        dp += v.x * q.x + v.y * q.y + v.z * q.z + v.w * q.w;
    }
    #pragma unroll
    for (int o = 16; o; o >>= 1) {
        ss += __shfl_xor_sync(0xFFFFFFFFu, ss, o);
        dp += __shfl_xor_sync(0xFFFFFFFFu, dp, o);
    }
    if (l == 0) {
        float inv = 1.0f / fmaxf(sqrtf(ss), 1e-12f);
        float s = dp * inv;
        g_invn[n] = inv;
        g_s[n] = s;
        int slot = (int)(n & 511);
        atomicAdd(&g_sfA[slot], s);
        atomicAdd(&g_sfB[slot], s * s);
    }
}

// ---------------- kernel 2: pass 2 with fused exp (P2B blocks x 256 thr) -----------
// reversed row order: consume the L2-resident tail of K left by pass 1 first.
// Tail: prefetch Wv+Wm (8 MB) into L2 so kern_post's GEMV phases hit L2.
__global__ void kern_pass2(const float* __restrict__ Kmat,
                           const float* __restrict__ Wv,
                           const float* __restrict__ Wm,
                           int N) {
    __shared__ float ws[P2ROWS];
    __shared__ float st[2];    // mean, rstd
    __shared__ float redA[8];
    __shared__ float redB[8];
    int t = threadIdx.x, w = t >> 5, l = t & 31;
    long n0 = (long)(P2B - 1 - blockIdx.x) * P2ROWS;

    if (blockIdx.x == 0 && t == 0) g_qkdone = 0;   // reset flag for next replay

    // finalize stats (redundant per block; 4 KB of L2-hit reads)
    {
        float sa = g_sfA[t] + g_sfA[t + 256];
        float sb = g_sfB[t] + g_sfB[t + 256];
        #pragma unroll
        for (int o = 16; o; o >>= 1) {
            sa += __shfl_xor_sync(0xFFFFFFFFu, sa, o);
            sb += __shfl_xor_sync(0xFFFFFFFFu, sb, o);
        }
        if (l == 0) { redA[w] = sa; redB[w] = sb; }
        __syncthreads();
        if (t == 0) {
            float A = 0.f, B = 0.f;
            #pragma unroll
            for (int i = 0; i < 8; i++) { A += redA[i]; B += redB[i]; }
            double mean = (double)A / N;
            double var  = ((double)B - (double)N * mean * mean) / (double)(N - 1);
            double sd   = sqrt(var > 0.0 ? var : 0.0);
            st[0] = (float)mean;
            st[1] = (float)(1.0 / (sd + 1e-8));
        }
        __syncthreads();
    }
    float mean = st[0], rstd = st[1];

    // this block's 128 weights: w = exp(clip(zscore)) * invn ; e-sum to g_epart
    float e = 0.f;
    if (t < P2ROWS) {
        float s   = g_s[n0 + t];
        float inv = g_invn[n0 + t];
        float x = fminf(fmaxf((s - mean) * rstd, -10.f), 10.f);
        e = expf(x);
        ws[t] = e * inv;
    }
    #pragma unroll
    for (int o = 16; o; o >>= 1) e += __shfl_xor_sync(0xFFFFFFFFu, e, o);
    if (l == 0) redA[w] = e;
    __syncthreads();
    if (t == 0) {
        float tot = 0.f;
        #pragma unroll
        for (int i = 0; i < 4; i++) tot += redA[i];   // warps 4..7 hold zeros
        g_epart[blockIdx.x] = tot;
    }
    __syncthreads();

    // weighted row-sum partials (1/denom deferred to kern_post)
    float4 acc = make_float4(0.f, 0.f, 0.f, 0.f);
    const float4* base = (const float4*)Kmat + n0 * (DIM / 4) + t;
    #pragma unroll 8
    for (int r = 0; r < P2ROWS; r++) {
        float wv = ws[r];
        float4 v = base[(long)r * (DIM / 4)];
        acc.x += wv * v.x;
        acc.y += wv * v.y;
        acc.z += wv * v.z;
        acc.w += wv * v.w;
    }
    ((float4*)g_zpart)[blockIdx.x * (DIM / 4) + t] = acc;

    // warm L2 for kern_post: 512 blocks x 128 lines x 128 B = 8 MB (Wv || Wm)
    if (t < 128) {
        size_t li = (size_t)blockIdx.x * 128 + t;
        const char* p = (li < 32768)
                      ? (const char*)Wv + li * 128
                      : (const char*)Wm + (li - 32768) * 128;
        asm volatile("prefetch.global.L2 [%0];" :: "l"(p));
    }
}

// ---------------- kernel 3: z-reduce + Wv GEMV + Wm GEMV + gate (128 x 256) --------
__global__ void kern_post(const float* __restrict__ Wv,
                          const float* __restrict__ Wm,
                          const float* __restrict__ bv,
                          const float* __restrict__ bm,
                          const float* __restrict__ q_init,
                          const float* __restrict__ gamma,
                          float* __restrict__ out) {
    __shared__ float cred[8][33];
    __shared__ float xs[8];
    __shared__ float red[8];
    __shared__ float invden_s;
    int b = blockIdx.x, t = threadIdx.x, w = t >> 5, l = t & 31;
    int j = t & 7, g = t >> 3;   // 8 cols x 32 groups

    // fused phase: denom partials + z-partial reduction in one load window
    {
        float e2 = g_epart[t] + g_epart[t + 256];
        float a = 0.f;
        #pragma unroll
        for (int k = 0; k < 16; k++)
            a += g_zpart[(g * 16 + k) * DIM + b * 8 + j];
        #pragma unroll
        for (int o = 16; o; o >>= 1) e2 += __shfl_xor_sync(0xFFFFFFFFu, e2, o);
        if (l == 0) red[w] = e2;
        cred[j][g] = a;
        __syncthreads();
        if (t == 0) {
            float tot = 0.f;
            #pragma unroll
            for (int i = 0; i < 8; i++) tot += red[i];
            invden_s = 1.0f / tot;
        }
        if (t < 8) {
            float s = 0.f;
            #pragma unroll
            for (int i = 0; i < 32; i++) s += cred[t][i];
            xs[t] = s;            // invden folded into GEMV below
        }
        __syncthreads();
    }
    float invden = invden_s;

    // Wv GEMV partial from z slice (8 d-rows), invden folded in
    {
        const float4* W4 = (const float4*)(Wv + (size_t)b * 8 * DIM) + t;
        float4 acc = make_float4(0.f, 0.f, 0.f, 0.f);
        #pragma unroll
        for (int d = 0; d < 8; d++) {
            float xv = xs[d] * invden;
            float4 v = W4[d * (DIM / 4)];
            acc.x += xv * v.x;
            acc.y += xv * v.y;
            acc.z += xv * v.z;
            acc.w += xv * v.w;
        }
        ((float4*)g_vpart)[b * (DIM / 4) + t] = acc;
    }

    grid_sync(&g_syncB, NBPOST);

    // ctx slice: bv + reduce of 128 v-partials over cols [b*8, b*8+8)
    {
        float a = 0.f;
        #pragma unroll
        for (int k = 0; k < 4; k++)
            a += g_vpart[(g * 4 + k) * DIM + b * 8 + j];
        cred[j][g] = a;
        __syncthreads();
        if (t < 8) {
            float s = bv[b * 8 + t];
            #pragma unroll
            for (int i = 0; i < 32; i++) s += cred[t][i];
            xs[t] = s;
        }
        __syncthreads();
    }

    // Wm GEMV partial from ctx slice
    {
        const float4* W4 = (const float4*)(Wm + (size_t)b * 8 * DIM) + t;
        float4 acc = make_float4(0.f, 0.f, 0.f, 0.f);
        #pragma unroll
        for (int d = 0; d < 8; d++) {
            float xv = xs[d];
            float4 v = W4[d * (DIM / 4)];
            acc.x += xv * v.x;
            acc.y += xv * v.y;
            acc.z += xv * v.z;
            acc.w += xv * v.w;
        }
        ((float4*)g_mpart)[b * (DIM / 4) + t] = acc;
    }

    grid_sync(&g_syncB, NBPOST);

    // final gate for out cols [b*8, b*8+8)
    {
        float a = 0.f;
        #pragma unroll
        for (int k = 0; k < 4; k++)
            a += g_mpart[(g * 4 + k) * DIM + b * 8 + j];
        cred[j][g] = a;
        __syncthreads();
        if (t < 8) {
            int c = b * 8 + t;
            float s = bm[c];
            #pragma unroll
            for (int i = 0; i < 32; i++) s += cred[t][i];
            float gg = 1.0f / (1.0f + expf(-gamma[0]));
            out[c] = gg * q_init[c] + (1.0f - gg) * s;
        }
    }
}

// ---------------- launcher ----------------------------------------------------------
extern "C" void kernel_launch(void* const* d_in, const int* in_sizes, int n_in,
                              void* d_out, int out_size) {
    const float* q_init = (const float*)d_in[0];
    const float* k_init = (const float*)d_in[1];
    const float* Wq     = (const float*)d_in[2];
    const float* bq     = (const float*)d_in[3];
    const float* Wk     = (const float*)d_in[4];
    // d_in[5] = bk: cancels under z-score normalization of scores
    const float* Wv     = (const float*)d_in[6];
    const float* bv     = (const float*)d_in[7];
    const float* Wm     = (const float*)d_in[8];
    const float* bm     = (const float*)d_in[9];
    const float* gamma  = (const float*)d_in[10];
    float* out = (float*)d_out;

    int N = in_sizes[1] / DIM;  // 65536

    kern_pass1<<<N / 8, 256>>>(k_init, q_init, Wq, Wk, bq);
    kern_pass2<<<P2B, 256>>>(k_init, Wv, Wm, N);
    kern_post <<<NBPOST, 256>>>(Wv, Wm, bv, bm, q_init, gamma, out);
}

// round 13
// speedup vs baseline: 1.0699x; 1.0699x over previous
#include <cuda_runtime.h>
#include <math.h>

#define DIM    1024
#define HALF   512
#define NMAX   65536
#define P2B    512          // pass2 blocks
#define P2ROWS 128          // rows per pass2 block
#define NBPRE  64           // pre-blocks inside pass1
#define NPOST  128          // post participants (last arrivals of pass2)

// ---------------- scratch (device globals) ----------------------------------------
__device__ float    g_qpart[NBPRE * HALF];   // Wq GEMV partials
__device__ float    g_qk[DIM];               // Wk @ q
__device__ float    g_s[NMAX];               // raw scores
__device__ float    g_invn[NMAX];            // 1/||k_init[n]||
__device__ float    g_sfA[512];              // score-sum slots
__device__ float    g_sfB[512];              // score-sumsq slots
__device__ float    g_epart[P2B];            // per-pass2-block exp sums
__device__ float    g_zpart[P2B * DIM];      // pass2 partial row-sums
__device__ float    g_vpart[NPOST * DIM];    // z@Wv partials
__device__ float    g_mpart[NPOST * DIM];    // ctx@Wm partials
__device__ unsigned g_syncA = 0;             // generation barrier (pre blocks)
__device__ unsigned g_syncB = 0;             // generation barrier (post participants)
__device__ unsigned g_done  = 0;             // monotonic pass2 completion counter
__device__ unsigned g_qkdone = 0;            // qk-ready flag (reset by pass2)

// ---------------- generation-based grid barrier (participants resident) ------------
__device__ __forceinline__ void grid_sync(unsigned* ctr, unsigned nb) {
    __syncthreads();
    if (threadIdx.x == 0) {
        __threadfence();
        unsigned old = atomicAdd(ctr, 1u);
        unsigned target = (old / nb + 1u) * nb;
        while (*(volatile unsigned*)ctr < target) __nanosleep(64);
        __threadfence();
    }
    __syncthreads();
}

// ---------------- kernel 1: fused pre + LEAN pass 1 (N/8 blocks x 256 thr) ---------
// Blocks 0..63 compute qk = Wk @ (l2norm(q_init)@Wq + bq), then raise the flag.
// ALL blocks then run the lean streaming loop (one float4 in flight, ss+dp fused).
__global__ void __launch_bounds__(256)
kern_pass1(const float* __restrict__ Kmat,
           const float* __restrict__ q_init,
           const float* __restrict__ Wq,
           const float* __restrict__ Wk,
           const float* __restrict__ bq) {
    __shared__ float sh[DIM + HALF];   // pre: qn|q ; pass1: qk in [0..DIM)
    __shared__ float red[8];
    int b = blockIdx.x, t = threadIdx.x, w = t >> 5, l = t & 31;

    // ===================== pre (blocks 0..63 only) =====================
    if (b < NBPRE) {
        if (t < 8) {                  // reset stat slots each replay
            g_sfA[b * 8 + t] = 0.f;
            g_sfB[b * 8 + t] = 0.f;
        }

        // q l2norm (redundant per pre-block; 4 KB, L2 hit)
        float4 v = ((const float4*)q_init)[t];
        float ss = v.x * v.x + v.y * v.y + v.z * v.z + v.w * v.w;
        #pragma unroll
        for (int o = 16; o; o >>= 1) ss += __shfl_xor_sync(0xFFFFFFFFu, ss, o);
        if (l == 0) red[w] = ss;
        __syncthreads();
        if (t == 0) {
            float tot = 0.f;
            #pragma unroll
            for (int i = 0; i < 8; i++) tot += red[i];
            red[0] = 1.0f / fmaxf(sqrtf(tot), 1e-12f);
        }
        __syncthreads();
        float inv = red[0];
        ((float4*)sh)[t] = make_float4(v.x * inv, v.y * inv, v.z * inv, v.w * inv);
        __syncthreads();

        // Wq GEMV partial: pre-block b owns d-rows [b*16, b*16+16); float2 cols
        {
            const float2* W2 = (const float2*)(Wq + (size_t)b * 16 * HALF);
            float2 a = make_float2(0.f, 0.f);
            #pragma unroll
            for (int d = 0; d < 16; d++) {
                float x = sh[b * 16 + d];
                float2 wv = W2[d * (HALF / 2) + t];
                a.x += x * wv.x;
                a.y += x * wv.y;
            }
            ((float2*)(g_qpart + b * HALF))[t] = a;
        }

        grid_sync(&g_syncA, NBPRE);   // among the 64 pre blocks (wave-1 resident)

        // combine q = bq + sum(partials) into sh[DIM..DIM+HALF)
        #pragma unroll
        for (int j = 0; j < 2; j++) {
            int c = t + j * 256;
            float acc = bq[c];
            #pragma unroll 16
            for (int p = 0; p < NBPRE; p++) acc += g_qpart[p * HALF + c];
            sh[DIM + c] = acc;
        }
        __syncthreads();

        // Wk GEMV: pre-block b owns qk rows [b*16, b*16+16); 8 warps x 2 rows
        #pragma unroll
        for (int r = 0; r < 2; r++) {
            int d = b * 16 + w * 2 + r;
            const float4* row = (const float4*)(Wk + (size_t)d * HALF);
            const float4* q4  = (const float4*)(sh + DIM);
            float acc = 0.f;
            #pragma unroll
            for (int i = 0; i < 4; i++) {
                float4 vv = row[i * 32 + l];
                float4 qq = q4[i * 32 + l];
                acc += vv.x * qq.x + vv.y * qq.y + vv.z * qq.z + vv.w * qq.w;
            }
            #pragma unroll
            for (int o = 16; o; o >>= 1) acc += __shfl_xor_sync(0xFFFFFFFFu, acc, o);
            if (l == 0) g_qk[d] = acc;
        }
        __syncthreads();
        if (t == 0) {
            __threadfence();
            atomicAdd(&g_qkdone, 1u);
        }
        __syncthreads();
    }

    // ===================== lean pass 1 (all blocks) =====================
    if (t == 0) {
        while (*(volatile unsigned*)&g_qkdone < (unsigned)NBPRE) __nanosleep(64);
    }
    __syncthreads();

    // qk into shared
    #pragma unroll
    for (int i = 0; i < 4; i++) sh[t + i * 256] = g_qk[t + i * 256];
    __syncthreads();

    long n = (long)b * 8 + w;
    const float4* row = (const float4*)(Kmat + n * DIM);
    const float4* q4  = (const float4*)sh;
    float ss = 0.f, dp = 0.f;
    #pragma unroll
    for (int i = 0; i < 8; i++) {
        float4 v = row[i * 32 + l];
        float4 q = q4[i * 32 + l];
        ss += v.x * v.x + v.y * v.y + v.z * v.z + v.w * v.w;
        dp += v.x * q.x + v.y * q.y + v.z * q.z + v.w * q.w;
    }
    #pragma unroll
    for (int o = 16; o; o >>= 1) {
        ss += __shfl_xor_sync(0xFFFFFFFFu, ss, o);
        dp += __shfl_xor_sync(0xFFFFFFFFu, dp, o);
    }
    if (l == 0) {
        float inv = 1.0f / fmaxf(sqrtf(ss), 1e-12f);
        float s = dp * inv;
        g_invn[n] = inv;
        g_s[n] = s;
        int slot = (int)(n & 511);
        atomicAdd(&g_sfA[slot], s);
        atomicAdd(&g_sfB[slot], s * s);
    }
}

// ---------------- kernel 2: pass 2 + gated post tail (P2B blocks x 256 thr) --------
// Stage A: stats + exp + weighted row-sum partials (reversed rows for L2 reuse).
// Then each block bumps a monotonic done counter; the LAST 128 arrivals continue
// into the post phases (z-reduce, Wv GEMV, ctx, Wm GEMV, gate) with vb = rank-384.
__global__ void __launch_bounds__(256, 4)
kern_pass2(const float* __restrict__ Kmat,
           const float* __restrict__ Wv,
           const float* __restrict__ Wm,
           const float* __restrict__ bv,
           const float* __restrict__ bm,
           const float* __restrict__ q_init,
           const float* __restrict__ gamma,
           float* __restrict__ out,
           int N) {
    __shared__ float ws[P2ROWS];
    __shared__ float st[2];
    __shared__ float redA[8];
    __shared__ float redB[8];
    __shared__ unsigned arr_sh;
    int t = threadIdx.x, w = t >> 5, l = t & 31;
    long n0 = (long)(P2B - 1 - blockIdx.x) * P2ROWS;

    if (blockIdx.x == 0 && t == 0) g_qkdone = 0;   // reset flag for next replay

    // ===== Stage A: stats finalize + weights + zpart =====
    {
        float sa = g_sfA[t] + g_sfA[t + 256];
        float sb = g_sfB[t] + g_sfB[t + 256];
        #pragma unroll
        for (int o = 16; o; o >>= 1) {
            sa += __shfl_xor_sync(0xFFFFFFFFu, sa, o);
            sb += __shfl_xor_sync(0xFFFFFFFFu, sb, o);
        }
        if (l == 0) { redA[w] = sa; redB[w] = sb; }
        __syncthreads();
        if (t == 0) {
            float A = 0.f, B = 0.f;
            #pragma unroll
            for (int i = 0; i < 8; i++) { A += redA[i]; B += redB[i]; }
            double mean = (double)A / N;
            double var  = ((double)B - (double)N * mean * mean) / (double)(N - 1);
            double sd   = sqrt(var > 0.0 ? var : 0.0);
            st[0] = (float)mean;
            st[1] = (float)(1.0 / (sd + 1e-8));
        }
        __syncthreads();
    }
    float mean = st[0], rstd = st[1];

    float e = 0.f;
    if (t < P2ROWS) {
        float s   = g_s[n0 + t];
        float inv = g_invn[n0 + t];
        float x = fminf(fmaxf((s - mean) * rstd, -10.f), 10.f);
        e = expf(x);
        ws[t] = e * inv;
    }
    #pragma unroll
    for (int o = 16; o; o >>= 1) e += __shfl_xor_sync(0xFFFFFFFFu, e, o);
    if (l == 0) redA[w] = e;
    __syncthreads();
    if (t == 0) {
        float tot = 0.f;
        #pragma unroll
        for (int i = 0; i < 4; i++) tot += redA[i];
        g_epart[blockIdx.x] = tot;
    }
    __syncthreads();

    {
        float4 acc = make_float4(0.f, 0.f, 0.f, 0.f);
        const float4* base = (const float4*)Kmat + n0 * (DIM / 4) + t;
        #pragma unroll 8
        for (int r = 0; r < P2ROWS; r++) {
            float wv = ws[r];
            float4 v = base[(long)r * (DIM / 4)];
            acc.x += wv * v.x;
            acc.y += wv * v.y;
            acc.z += wv * v.z;
            acc.w += wv * v.w;
        }
        ((float4*)g_zpart)[blockIdx.x * (DIM / 4) + t] = acc;
    }

    // ===== arrival gate: last NPOST arrivals continue as post participants =====
    __threadfence();
    __syncthreads();
    if (t == 0) arr_sh = atomicAdd(&g_done, 1u);
    __syncthreads();
    unsigned arr = arr_sh;
    unsigned rank = arr % (unsigned)P2B;
    if (rank < (unsigned)(P2B - NPOST)) return;   // early finishers exit

    int vb = (int)rank - (P2B - NPOST);           // 0..127, unique this replay
    unsigned target = arr - rank + (unsigned)P2B; // this replay's completion count
    if (t == 0) {
        while (*(volatile unsigned*)&g_done < target) __nanosleep(64);
        __threadfence();
    }
    __syncthreads();

    // ===== post phases (128 participants, vb = virtual block id) =====
    __shared__ float cred[8][33];
    __shared__ float xs[8];
    __shared__ float invden_s;
    int j = t & 7, g = t >> 3;   // 8 cols x 32 groups

    // fused: denom partials + z-partial reduction
    {
        float e2 = g_epart[t] + g_epart[t + 256];
        float a = 0.f;
        #pragma unroll
        for (int k = 0; k < 16; k++)
            a += g_zpart[(g * 16 + k) * DIM + vb * 8 + j];
        #pragma unroll
        for (int o = 16; o; o >>= 1) e2 += __shfl_xor_sync(0xFFFFFFFFu, e2, o);
        if (l == 0) redA[w] = e2;
        cred[j][g] = a;
        __syncthreads();
        if (t == 0) {
            float tot = 0.f;
            #pragma unroll
            for (int i = 0; i < 8; i++) tot += redA[i];
            invden_s = 1.0f / tot;
        }
        if (t < 8) {
            float s = 0.f;
            #pragma unroll
            for (int i = 0; i < 32; i++) s += cred[t][i];
            xs[t] = s;            // invden folded into GEMV below
        }
        __syncthreads();
    }
    float invden = invden_s;

    // Wv GEMV partial from z slice (8 d-rows), invden folded in
    {
        const float4* W4 = (const float4*)(Wv + (size_t)vb * 8 * DIM) + t;
        float4 acc = make_float4(0.f, 0.f, 0.f, 0.f);
        #pragma unroll
        for (int d = 0; d < 8; d++) {
            float xv = xs[d] * invden;
            float4 v = W4[d * (DIM / 4)];
            acc.x += xv * v.x;
            acc.y += xv * v.y;
            acc.z += xv * v.z;
            acc.w += xv * v.w;
        }
        ((float4*)g_vpart)[vb * (DIM / 4) + t] = acc;
    }

    grid_sync(&g_syncB, NPOST);

    // ctx slice: bv + reduce of 128 v-partials over cols [vb*8, vb*8+8)
    {
        float a = 0.f;
        #pragma unroll
        for (int k = 0; k < 4; k++)
            a += g_vpart[(g * 4 + k) * DIM + vb * 8 + j];
        cred[j][g] = a;
        __syncthreads();
        if (t < 8) {
            float s = bv[vb * 8 + t];
            #pragma unroll
            for (int i = 0; i < 32; i++) s += cred[t][i];
            xs[t] = s;
        }
        __syncthreads();
    }

    // Wm GEMV partial from ctx slice
    {
        const float4* W4 = (const float4*)(Wm + (size_t)vb * 8 * DIM) + t;
        float4 acc = make_float4(0.f, 0.f, 0.f, 0.f);
        #pragma unroll
        for (int d = 0; d < 8; d++) {
            float xv = xs[d];
            float4 v = W4[d * (DIM / 4)];
            acc.x += xv * v.x;
            acc.y += xv * v.y;
            acc.z += xv * v.z;
            acc.w += xv * v.w;
        }
        ((float4*)g_mpart)[vb * (DIM / 4) + t] = acc;
    }

    grid_sync(&g_syncB, NPOST);

    // final gate for out cols [vb*8, vb*8+8)
    {
        float a = 0.f;
        #pragma unroll
        for (int k = 0; k < 4; k++)
            a += g_mpart[(g * 4 + k) * DIM + vb * 8 + j];
        cred[j][g] = a;
        __syncthreads();
        if (t < 8) {
            int c = vb * 8 + t;
            float s = bm[c];
            #pragma unroll
            for (int i = 0; i < 32; i++) s += cred[t][i];
            float gg = 1.0f / (1.0f + expf(-gamma[0]));
            out[c] = gg * q_init[c] + (1.0f - gg) * s;
        }
    }
}

// ---------------- launcher ----------------------------------------------------------
extern "C" void kernel_launch(void* const* d_in, const int* in_sizes, int n_in,
                              void* d_out, int out_size) {
    const float* q_init = (const float*)d_in[0];
    const float* k_init = (const float*)d_in[1];
    const float* Wq     = (const float*)d_in[2];
    const float* bq     = (const float*)d_in[3];
    const float* Wk     = (const float*)d_in[4];
    // d_in[5] = bk: cancels under z-score normalization of scores
    const float* Wv     = (const float*)d_in[6];
    const float* bv     = (const float*)d_in[7];
    const float* Wm     = (const float*)d_in[8];
    const float* bm     = (const float*)d_in[9];
    const float* gamma  = (const float*)d_in[10];
    float* out = (float*)d_out;

    int N = in_sizes[1] / DIM;  // 65536

    kern_pass1<<<N / 8, 256>>>(k_init, q_init, Wq, Wk, bq);
    kern_pass2<<<P2B, 256>>>(k_init, Wv, Wm, bv, bm, q_init, gamma, out, N);
}